// round 17
// baseline (speedup 1.0000x reference)
#include <cuda_runtime.h>
#include <cuda_bf16.h>
#include <cuda_fp16.h>
#include <cuda_fp8.h>
#include <cstdint>
#include <cstddef>

// ---------------- problem constants ----------------
#define INDIM  1024
#define OUTDIM 2048
#define BATCH  8192

#define BM 128
#define BN 128
#define BK 128                   // fp8 elems per stage = 128 B row (swizzle atom)
#define NSTAGE_K (INDIM / BK)    // 8
#define STAGES 3
#define GEMM_THREADS 256

// P is scaled by 32 before fp8 quantization; epilogue multiplies acc by 2/32.
#define ACC_SCALE 0.0625f

#define SMEM_PSQ_OFF   0u
#define SMEM_TILES_OFF 1024u
#define STAGE_BYTES    ((BM + BN) * 128u)                       // 32768
#define SMEM_TOTAL     (SMEM_TILES_OFF + STAGES * STAGE_BYTES)  // 99328 (x2 CTAs = 194KB/SM)

// wave-quantization split: 296 slots (148 SM x 2 CTA); 888 = 3 full waves
#define N_TILES      1024
#define FULL_TILES   888
#define TAIL_TILES   (N_TILES - FULL_TILES)    // 136
#define TAIL_BLOCKS  (TAIL_TILES * 2)          // 272 half-tiles (128x64)

// prep grid split
#define CONV_BLOCKS  (BATCH / 16)         // 512 blocks, 16 rows each (warp handles 2 rows)
#define TR_NBLK      (OUTDIM / 32)        // 64 n-blocks of 32
#define TR_KBLK      (INDIM / 128)        // 8 k-blocks of 128
#define TR_BLOCKS    (TR_NBLK * TR_KBLK)  // 512
#define PREP_BLOCKS  (CONV_BLOCKS + TR_BLOCKS)   // 1024

// ---------------- device scratch (alloc-free) ----------------
__device__ __align__(128) uint8_t g_x_fp8[(size_t)BATCH * INDIM];   // 8 MB, e4m3
__device__ __align__(128) uint8_t g_pt_fp8[(size_t)OUTDIM * INDIM]; // 2 MB, [n][k], e4m3 of 32*p
__device__ float g_x_sq[BATCH];
__device__ float g_psq_part[TR_KBLK][OUTDIM];   // 64 KB partial column norms

// ---------------- helpers ----------------
__device__ __forceinline__ uint32_t smem_to_u32(const void* p) {
    uint32_t a;
    asm("{ .reg .u64 t; cvta.to.shared.u64 t, %1; cvt.u32.u64 %0, t; }" : "=r"(a) : "l"(p));
    return a;
}
__device__ __forceinline__ uint32_t sw128(uint32_t off) {
    return off ^ ((off >> 3) & 0x70);
}
__device__ __forceinline__ void cp_async16(uint32_t dst, const void* src) {
    asm volatile("cp.async.cg.shared.global [%0], [%1], 16;" :: "r"(dst), "l"(src) : "memory");
}
#define CP_COMMIT() asm volatile("cp.async.commit_group;" ::: "memory")
#define CP_WAIT(n)  asm volatile("cp.async.wait_group %0;" :: "n"(n) : "memory")

__device__ __forceinline__ void ldmatrix_x4(uint32_t* r, uint32_t addr) {
    asm volatile("ldmatrix.sync.aligned.m8n8.x4.shared.b16 {%0,%1,%2,%3}, [%4];"
                 : "=r"(r[0]), "=r"(r[1]), "=r"(r[2]), "=r"(r[3]) : "r"(addr));
}
// fp8 e4m3 MMA with fp16 accumulator (2 packed f16x2 regs).
__device__ __forceinline__ void mma_fp8_h(uint32_t* c, const uint32_t* a, const uint32_t* b) {
    asm volatile(
        "mma.sync.aligned.m16n8k32.row.col.f16.e4m3.e4m3.f16 "
        "{%0,%1}, {%2,%3,%4,%5}, {%6,%7}, {%0,%1};"
        : "+r"(c[0]), "+r"(c[1])
        : "r"(a[0]), "r"(a[1]), "r"(a[2]), "r"(a[3]), "r"(b[0]), "r"(b[1]));
}

__device__ __forceinline__ uint8_t to_e4m3(float v) {
    return (uint8_t)__nv_cvt_float_to_fp8(v, __NV_SATFINITE, __NV_E4M3);
}

// ---------------- fused prep kernel (R16 verbatim) ----------------
__global__ void prep_kernel(const float* __restrict__ x, const float* __restrict__ p) {
    const int tid = threadIdx.x;
    if ((int)blockIdx.x < CONV_BLOCKS) {
        const int warp = tid >> 5, lane = tid & 31;
        const int row0 = blockIdx.x * 16 + warp * 2;
        const float4* xr0 = reinterpret_cast<const float4*>(x + (size_t)row0 * INDIM);
        const float4* xr1 = reinterpret_cast<const float4*>(x + (size_t)(row0 + 1) * INDIM);
        uchar4* dst0 = reinterpret_cast<uchar4*>(g_x_fp8 + (size_t)row0 * INDIM);
        uchar4* dst1 = reinterpret_cast<uchar4*>(g_x_fp8 + (size_t)(row0 + 1) * INDIM);
        float4 v0[8], v1[8];
#pragma unroll
        for (int j = 0; j < 8; j++) { v0[j] = xr0[lane + 32 * j]; v1[j] = xr1[lane + 32 * j]; }
        float a0 = 0.f, a1 = 0.f;
#pragma unroll
        for (int j = 0; j < 8; j++) {
            a0 += v0[j].x * v0[j].x + v0[j].y * v0[j].y + v0[j].z * v0[j].z + v0[j].w * v0[j].w;
            a1 += v1[j].x * v1[j].x + v1[j].y * v1[j].y + v1[j].z * v1[j].z + v1[j].w * v1[j].w;
            uchar4 q0, q1;
            q0.x = to_e4m3(v0[j].x); q0.y = to_e4m3(v0[j].y);
            q0.z = to_e4m3(v0[j].z); q0.w = to_e4m3(v0[j].w);
            q1.x = to_e4m3(v1[j].x); q1.y = to_e4m3(v1[j].y);
            q1.z = to_e4m3(v1[j].z); q1.w = to_e4m3(v1[j].w);
            dst0[lane + 32 * j] = q0;
            dst1[lane + 32 * j] = q1;
        }
#pragma unroll
        for (int o = 16; o > 0; o >>= 1) {
            a0 += __shfl_xor_sync(0xFFFFFFFFu, a0, o);
            a1 += __shfl_xor_sync(0xFFFFFFFFu, a1, o);
        }
        if (lane == 0) { g_x_sq[row0] = a0; g_x_sq[row0 + 1] = a1; }
    } else {
        __shared__ float tile[128][33];
        __shared__ float partial[8][33];
        const int b2 = blockIdx.x - CONV_BLOCKS;
        const int n0 = (b2 % TR_NBLK) * 32;
        const int k_blk = b2 / TR_NBLK;
        const int k0 = k_blk * 128;
        const int lane = tid & 31, w = tid >> 5;
#pragma unroll
        for (int kk = 0; kk < 128; kk += 8)
            tile[kk + w][lane] = p[(size_t)(k0 + kk + w) * OUTDIM + n0 + lane];
        __syncthreads();
        {
            union { uint4 u; uint8_t b[16]; } pk;
            float sq = 0.f;
#pragma unroll
            for (int j = 0; j < 16; j++) {
                float v = tile[w * 16 + j][lane];
                sq += v * v;
                pk.b[j] = to_e4m3(32.0f * v);
            }
            *reinterpret_cast<uint4*>(g_pt_fp8 + (size_t)(n0 + lane) * INDIM + k0 + w * 16) = pk.u;
            partial[w][lane] = sq;
        }
        __syncthreads();
        if (w == 0) {
            float s = 0.f;
#pragma unroll
            for (int j = 0; j < 8; j++) s += partial[j][lane];
            g_psq_part[k_blk][n0 + lane] = s;
        }
    }
}

// ---------------- stage loader (full 128x128 tiles) ----------------
__device__ __forceinline__ void load_stage(uint32_t smem_base, int buf, int m0, int n0,
                                           int k0, int tid) {
    uint32_t a_s = smem_base + SMEM_TILES_OFF + (uint32_t)buf * STAGE_BYTES;
    uint32_t b_s = a_s + BM * 128u;
    const uint8_t* abase = g_x_fp8 + (size_t)m0 * INDIM + k0;
#pragma unroll
    for (int i = 0; i < 4; i++) {
        int idx = tid + i * GEMM_THREADS;
        int r = idx >> 3, c = idx & 7;
        cp_async16(a_s + sw128((uint32_t)(r * 128 + c * 16)),
                   abase + (size_t)r * INDIM + c * 16);
    }
    const uint8_t* bbase = g_pt_fp8 + (size_t)n0 * INDIM + k0;
#pragma unroll
    for (int i = 0; i < 4; i++) {
        int idx = tid + i * GEMM_THREADS;
        int r = idx >> 3, c = idx & 7;
        cp_async16(b_s + sw128((uint32_t)(r * 128 + c * 16)),
                   bbase + (size_t)r * INDIM + c * 16);
    }
}

// ---------------- GEMM A: champion config, first 888 tiles (3 exact waves) ------
__global__ void __launch_bounds__(GEMM_THREADS, 2)
gemm_kernel(float* __restrict__ out) {
    extern __shared__ char smem[];
    uint32_t smem_base = smem_to_u32(smem);
    const int tid = threadIdx.x;
    const int wid = tid >> 5;
    const int lid = tid & 31;
    const int wm = wid & 3;
    const int wn = wid >> 2;
    const int t  = blockIdx.x;         // linear tile id 0..887
    const int n0 = (t & 15) * BN;
    const int m0 = (t >> 4) * BM;

#pragma unroll
    for (int s = 0; s < STAGES - 1; s++) {
        load_stage(smem_base, s, m0, n0, s * BK, tid);
        CP_COMMIT();
    }

    for (int i = tid; i < BN; i += GEMM_THREADS) {
        float s0 = 0.f, s1 = 0.f, s2 = 0.f, s3 = 0.f;
#pragma unroll
        for (int j = 0; j < TR_KBLK; j += 4) {
            s0 += g_psq_part[j + 0][n0 + i];
            s1 += g_psq_part[j + 1][n0 + i];
            s2 += g_psq_part[j + 2][n0 + i];
            s3 += g_psq_part[j + 3][n0 + i];
        }
        *reinterpret_cast<float*>(smem + SMEM_PSQ_OFF + i * 4) = (s0 + s1) + (s2 + s3);
    }

    uint32_t acc[2][8][2];
#pragma unroll
    for (int mi = 0; mi < 2; mi++)
#pragma unroll
        for (int nt = 0; nt < 8; nt++) { acc[mi][nt][0] = 0u; acc[mi][nt][1] = 0u; }

    const int a_row = wm * 32 + (lid & 15);
    const int a_kb  = (lid >> 4) * 16;
    const int sub   = lid >> 3;
    const int b_row = wn * 64 + (sub >> 1) * 8 + (lid & 7);
    const int b_kb  = (sub & 1) * 16;

    int buf = 0, pbuf = STAGES - 1;
    for (int s = 0; s < NSTAGE_K; s++) {
        CP_WAIT(STAGES - 2);
        __syncthreads();
        if (s + STAGES - 1 < NSTAGE_K)
            load_stage(smem_base, pbuf, m0, n0, (s + STAGES - 1) * BK, tid);
        CP_COMMIT();

        const uint32_t t_s = smem_base + SMEM_TILES_OFF + (uint32_t)buf * STAGE_BYTES;
        const uint32_t a_s = t_s;
        const uint32_t b_s = t_s + BM * 128u;

#pragma unroll
        for (int ks = 0; ks < 4; ks++) {
            const int k0b = ks * 32;
            uint32_t afrag[2][4];
#pragma unroll
            for (int mi = 0; mi < 2; mi++) {
                uint32_t off = (uint32_t)((a_row + mi * 16) * 128 + k0b + a_kb);
                ldmatrix_x4(afrag[mi], a_s + sw128(off));
            }
            uint32_t bfrag[8][2];
#pragma unroll
            for (int nj = 0; nj < 4; nj++) {
                uint32_t off = (uint32_t)((b_row + nj * 16) * 128 + k0b + b_kb);
                uint32_t tt[4];
                ldmatrix_x4(tt, b_s + sw128(off));
                bfrag[nj * 2][0] = tt[0]; bfrag[nj * 2][1] = tt[1];
                bfrag[nj * 2 + 1][0] = tt[2]; bfrag[nj * 2 + 1][1] = tt[3];
            }
#pragma unroll
            for (int mi = 0; mi < 2; mi++)
#pragma unroll
                for (int nt = 0; nt < 8; nt++)
                    mma_fp8_h(acc[mi][nt], afrag[mi], bfrag[nt]);
        }
        buf = (buf + 1 == STAGES) ? 0 : buf + 1;
        pbuf = (pbuf + 1 == STAGES) ? 0 : pbuf + 1;
    }

    const float* psq_s = reinterpret_cast<const float*>(smem + SMEM_PSQ_OFF);
    const int lane4 = lid >> 2;
    const int lane2 = (lid & 3) * 2;
#pragma unroll
    for (int mi = 0; mi < 2; mi++) {
#pragma unroll
        for (int h = 0; h < 2; h++) {
            const int r = m0 + wm * 32 + mi * 16 + lane4 + h * 8;
            const float xs = g_x_sq[r];
            float* orow = out + (size_t)r * OUTDIM + n0 + wn * 64;
#pragma unroll
            for (int nt = 0; nt < 8; nt++) {
                const int cn = nt * 8 + lane2;
                __half2 hv = *reinterpret_cast<const __half2*>(&acc[mi][nt][h]);
                float2 w;
                w.x = fmaf(ACC_SCALE, __half2float(__low2half(hv)),
                           -xs - psq_s[wn * 64 + cn]);
                w.y = fmaf(ACC_SCALE, __half2float(__high2half(hv)),
                           -xs - psq_s[wn * 64 + cn + 1]);
                *reinterpret_cast<float2*>(orow + cn) = w;
            }
        }
    }
}

// ---------------- GEMM B: tail, 128x64 half-tiles (272 CTAs, ~0.55 wave) --------
__global__ void __launch_bounds__(GEMM_THREADS, 2)
gemm_tail_kernel(float* __restrict__ out) {
    extern __shared__ char smem[];
    uint32_t smem_base = smem_to_u32(smem);
    const int tid = threadIdx.x;
    const int wid = tid >> 5;
    const int lid = tid & 31;
    const int wm = wid & 3;
    const int wn = wid >> 2;            // 2 warps x 32 cols
    const int j  = blockIdx.x;          // 0..271
    const int t  = FULL_TILES + (j >> 1);
    const int half = j & 1;
    const int n0 = (t & 15) * BN + half * 64;   // 64-wide slice
    const int m0 = (t >> 4) * BM;

    // prologue: A 4 chunks, B 2 chunks (64 rows)
#pragma unroll
    for (int s = 0; s < STAGES - 1; s++) {
        uint32_t a_s = smem_base + SMEM_TILES_OFF + (uint32_t)s * STAGE_BYTES;
        uint32_t b_s = a_s + BM * 128u;
        const uint8_t* abase = g_x_fp8 + (size_t)m0 * INDIM + s * BK;
#pragma unroll
        for (int i = 0; i < 4; i++) {
            int idx = tid + i * GEMM_THREADS;
            int r = idx >> 3, c = idx & 7;
            cp_async16(a_s + sw128((uint32_t)(r * 128 + c * 16)),
                       abase + (size_t)r * INDIM + c * 16);
        }
        const uint8_t* bbase = g_pt_fp8 + (size_t)n0 * INDIM + s * BK;
#pragma unroll
        for (int i = 0; i < 2; i++) {
            int idx = tid + i * GEMM_THREADS;
            int r = idx >> 3, c = idx & 7;
            cp_async16(b_s + sw128((uint32_t)(r * 128 + c * 16)),
                       bbase + (size_t)r * INDIM + c * 16);
        }
        CP_COMMIT();
    }

    for (int i = tid; i < 64; i += GEMM_THREADS) {
        float s0 = 0.f, s1 = 0.f, s2 = 0.f, s3 = 0.f;
#pragma unroll
        for (int jj = 0; jj < TR_KBLK; jj += 4) {
            s0 += g_psq_part[jj + 0][n0 + i];
            s1 += g_psq_part[jj + 1][n0 + i];
            s2 += g_psq_part[jj + 2][n0 + i];
            s3 += g_psq_part[jj + 3][n0 + i];
        }
        *reinterpret_cast<float*>(smem + SMEM_PSQ_OFF + i * 4) = (s0 + s1) + (s2 + s3);
    }

    uint32_t acc[2][4][2];
#pragma unroll
    for (int mi = 0; mi < 2; mi++)
#pragma unroll
        for (int nt = 0; nt < 4; nt++) { acc[mi][nt][0] = 0u; acc[mi][nt][1] = 0u; }

    const int a_row = wm * 32 + (lid & 15);
    const int a_kb  = (lid >> 4) * 16;
    const int sub   = lid >> 3;
    const int b_row = wn * 32 + (sub >> 1) * 8 + (lid & 7);   // + nj*16, 32 cols/warp
    const int b_kb  = (sub & 1) * 16;

    int buf = 0, pbuf = STAGES - 1;
    for (int s = 0; s < NSTAGE_K; s++) {
        CP_WAIT(STAGES - 2);
        __syncthreads();
        if (s + STAGES - 1 < NSTAGE_K) {
            uint32_t a_s = smem_base + SMEM_TILES_OFF + (uint32_t)pbuf * STAGE_BYTES;
            uint32_t b_s = a_s + BM * 128u;
            const uint8_t* abase = g_x_fp8 + (size_t)m0 * INDIM + (s + STAGES - 1) * BK;
#pragma unroll
            for (int i = 0; i < 4; i++) {
                int idx = tid + i * GEMM_THREADS;
                int r = idx >> 3, c = idx & 7;
                cp_async16(a_s + sw128((uint32_t)(r * 128 + c * 16)),
                           abase + (size_t)r * INDIM + c * 16);
            }
            const uint8_t* bbase = g_pt_fp8 + (size_t)n0 * INDIM + (s + STAGES - 1) * BK;
#pragma unroll
            for (int i = 0; i < 2; i++) {
                int idx = tid + i * GEMM_THREADS;
                int r = idx >> 3, c = idx & 7;
                cp_async16(b_s + sw128((uint32_t)(r * 128 + c * 16)),
                           bbase + (size_t)r * INDIM + c * 16);
            }
        }
        CP_COMMIT();

        const uint32_t t_s = smem_base + SMEM_TILES_OFF + (uint32_t)buf * STAGE_BYTES;
        const uint32_t a_s = t_s;
        const uint32_t b_s = t_s + BM * 128u;

#pragma unroll
        for (int ks = 0; ks < 4; ks++) {
            const int k0b = ks * 32;
            uint32_t afrag[2][4];
#pragma unroll
            for (int mi = 0; mi < 2; mi++) {
                uint32_t off = (uint32_t)((a_row + mi * 16) * 128 + k0b + a_kb);
                ldmatrix_x4(afrag[mi], a_s + sw128(off));
            }
            uint32_t bfrag[4][2];
#pragma unroll
            for (int nj = 0; nj < 2; nj++) {
                uint32_t off = (uint32_t)((b_row + nj * 16) * 128 + k0b + b_kb);
                uint32_t tt[4];
                ldmatrix_x4(tt, b_s + sw128(off));
                bfrag[nj * 2][0] = tt[0]; bfrag[nj * 2][1] = tt[1];
                bfrag[nj * 2 + 1][0] = tt[2]; bfrag[nj * 2 + 1][1] = tt[3];
            }
#pragma unroll
            for (int mi = 0; mi < 2; mi++)
#pragma unroll
                for (int nt = 0; nt < 4; nt++)
                    mma_fp8_h(acc[mi][nt], afrag[mi], bfrag[nt]);
        }
        buf = (buf + 1 == STAGES) ? 0 : buf + 1;
        pbuf = (pbuf + 1 == STAGES) ? 0 : pbuf + 1;
    }

    const float* psq_s = reinterpret_cast<const float*>(smem + SMEM_PSQ_OFF);
    const int lane4 = lid >> 2;
    const int lane2 = (lid & 3) * 2;
#pragma unroll
    for (int mi = 0; mi < 2; mi++) {
#pragma unroll
        for (int h = 0; h < 2; h++) {
            const int r = m0 + wm * 32 + mi * 16 + lane4 + h * 8;
            const float xs = g_x_sq[r];
            float* orow = out + (size_t)r * OUTDIM + n0 + wn * 32;
#pragma unroll
            for (int nt = 0; nt < 4; nt++) {
                const int cn = nt * 8 + lane2;
                __half2 hv = *reinterpret_cast<const __half2*>(&acc[mi][nt][h]);
                float2 w;
                w.x = fmaf(ACC_SCALE, __half2float(__low2half(hv)),
                           -xs - psq_s[wn * 32 + cn]);
                w.y = fmaf(ACC_SCALE, __half2float(__high2half(hv)),
                           -xs - psq_s[wn * 32 + cn + 1]);
                *reinterpret_cast<float2*>(orow + cn) = w;
            }
        }
    }
}

// ---------------- launch ----------------
extern "C" void kernel_launch(void* const* d_in, const int* in_sizes, int n_in,
                              void* d_out, int out_size) {
    const float* x = (const float*)d_in[0];
    const float* p = (const float*)d_in[1];
    if (n_in >= 2 && in_sizes[0] == OUTDIM * INDIM && in_sizes[1] == BATCH * INDIM) {
        x = (const float*)d_in[1];
        p = (const float*)d_in[0];
    }
    float* out = (float*)d_out;

    prep_kernel<<<PREP_BLOCKS, 256>>>(x, p);

    cudaFuncSetAttribute(gemm_kernel, cudaFuncAttributeMaxDynamicSharedMemorySize,
                         SMEM_TOTAL);
    cudaFuncSetAttribute(gemm_tail_kernel, cudaFuncAttributeMaxDynamicSharedMemorySize,
                         SMEM_TOTAL);
    gemm_kernel<<<FULL_TILES, GEMM_THREADS, SMEM_TOTAL>>>(out);
    gemm_tail_kernel<<<TAIL_BLOCKS, GEMM_THREADS, SMEM_TOTAL>>>(out);
}